// round 16
// baseline (speedup 1.0000x reference)
#include <cuda_runtime.h>
#include <cstdint>

#define LEN      2048
#define BM       256      // query rows per CTA
#define BN       64       // kv rows per tile
#define NKV      (LEN / BN)
#define NTHREADS 256

// strides (32-bit words)
#define SQR  260   // raw Q staging: [64 c][260] floats (prologue only)
#define SRAW 68    // raw K/V: [64][68] floats (single buffer each)
#define SQH  264   // packed Q half2: [32 c2][264]
#define SKH  72    // packed K half2: [32 c2][72]
#define SVH  72    // packed V half2: [32 s2][72]

// smem word layout
#define OFF_QH  0                      // 32*264 = 8448
#define OFF_KH  8448                   // 2 * 2304 = 4608 (double-buffered packed K)
#define OFF_VH  13056                  // 2 * 2304 = 4608 (double-buffered packed V)
#define OFF_RK  17664                  // 64*68 = 4352 (single raw K)
#define OFF_RV  22016                  // 64*68 = 4352 (single raw V)
#define SMEM_WORDS 26368
#define SMEM_BYTES (SMEM_WORDS * 4)    // 105472

// raw-Q staging (prologue only) spans [8448, 25088) — KH/VH/RK regions, free then
#define OFF_RAWQ 8448
#define PKBUF 2304                     // packed K/V buffer words (32*72)

__device__ __forceinline__ uint32_t pack_h2(float lo, float hi) {
    uint32_t d;
    asm("cvt.rn.f16x2.f32 %0, %1, %2;" : "=r"(d) : "f"(hi), "f"(lo));
    return d;
}
__device__ __forceinline__ float ex2f(float x) {
    float y;
    asm("ex2.approx.ftz.f32 %0, %1;" : "=f"(y) : "f"(x));
    return y;
}
__device__ __forceinline__ void mma_f16(float c[4], const uint32_t a[4],
                                        uint32_t b0, uint32_t b1) {
    asm volatile(
        "mma.sync.aligned.m16n8k16.row.col.f32.f16.f16.f32 "
        "{%0,%1,%2,%3}, {%4,%5,%6,%7}, {%8,%9}, {%0,%1,%2,%3};"
        : "+f"(c[0]), "+f"(c[1]), "+f"(c[2]), "+f"(c[3])
        : "r"(a[0]), "r"(a[1]), "r"(a[2]), "r"(a[3]), "r"(b0), "r"(b1));
}
__device__ __forceinline__ void cp_async16(uint32_t dst, const void* src) {
    asm volatile("cp.async.cg.shared.global [%0], [%1], 16;" :: "r"(dst), "l"(src));
}
__device__ __forceinline__ void cp_commit()  { asm volatile("cp.async.commit_group;" ::: "memory"); }
__device__ __forceinline__ void cp_wait_all(){ asm volatile("cp.async.wait_group 0;" ::: "memory"); }

__global__ void __launch_bounds__(NTHREADS, 1)
attn_f16_pipe(const float* __restrict__ qkv, float* __restrict__ out)
{
    const int qt   = blockIdx.x;          // 0..7 (256 q-rows)
    const int bh   = blockIdx.y;          // 0..31
    const int b    = bh >> 3;
    const int hd   = bh & 7;
    const int tid  = threadIdx.x;
    const int warp = tid >> 5;            // owns rows warp*32 .. +32
    const int lane = tid & 31;
    const int g    = lane >> 2;
    const int quad = lane & 3;

    const float* qbase = qkv + ((size_t)b * 1536 + (size_t)hd * 192) * LEN;
    const float* kbase = qbase + (size_t)64 * LEN;
    const float* vbase = qbase + (size_t)128 * LEN;
    const int t0 = qt * BM;

    extern __shared__ float smem[];
    float*    rawQ = smem + OFF_RAWQ;           // prologue only
    uint32_t* Qh   = (uint32_t*)(smem + OFF_QH);
    uint32_t* KhB  = (uint32_t*)(smem + OFF_KH);
    uint32_t* VhB  = (uint32_t*)(smem + OFF_VH);
    const float* rk = smem + OFF_RK;
    const float* rv = smem + OFF_RV;

    const uint32_t rawQ_u = (uint32_t)__cvta_generic_to_shared(rawQ);
    const uint32_t rawK_u = (uint32_t)__cvta_generic_to_shared(smem + OFF_RK);
    const uint32_t rawV_u = (uint32_t)__cvta_generic_to_shared(smem + OFF_RV);

    const float qscale = 0.125f * 1.44269504088896340736f;  // scale * log2(e)

    // self-matched raw K/V load constants: thread loads EXACTLY what it packs
    const int kc0 = 2 * (tid >> 4);       // K base row
    const int kf  = (tid & 15) * 4;       // K float offset
    const int vd  = tid & 63;             // V row
    const int vf0 = (tid >> 6) * 4;       // V base float offset

    // ---- prologue 1: raw Q [64 c][256 t] ----
    #pragma unroll
    for (int j = 0; j < 16; ++j) {              // 4096 float4
        int i = tid + j * NTHREADS;
        int c = i >> 6, f = i & 63;
        cp_async16(rawQ_u + (uint32_t)(c * SQR + f * 4) * 4,
                   qbase + (size_t)c * LEN + t0 + f * 4);
    }
    cp_commit();
    cp_wait_all();
    __syncthreads();

    // ---- pack Q -> half2 [c2][t], scale folded ----
    #pragma unroll
    for (int j = 0; j < 8; ++j) {
        int i = tid + j * NTHREADS;
        int c2 = i >> 6, f = i & 63;            // t = 4f
        const float4 a = *(const float4*)(rawQ + (2 * c2) * SQR + 4 * f);
        const float4 d = *(const float4*)(rawQ + (2 * c2 + 1) * SQR + 4 * f);
        uint4 w;
        w.x = pack_h2(a.x * qscale, d.x * qscale);
        w.y = pack_h2(a.y * qscale, d.y * qscale);
        w.z = pack_h2(a.z * qscale, d.z * qscale);
        w.w = pack_h2(a.w * qscale, d.w * qscale);
        *(uint4*)(Qh + c2 * SQH + 4 * f) = w;
    }
    __syncthreads();   // staging consumed; KH/VH/RK/RV regions free

    // ---- prologue 2: raw K0/V0 (self-matched mapping) ----
    #pragma unroll
    for (int j = 0; j < 4; ++j) {               // K rows 2c2, 2c2+1, +32, +33
        int c = kc0 + (j & 1) + 32 * (j >> 1);
        cp_async16(rawK_u + (uint32_t)(c * SRAW + kf) * 4,
                   kbase + (size_t)c * LEN + kf);
    }
    #pragma unroll
    for (int j = 0; j < 4; ++j) {               // V row vd, offsets vf0+16j
        int f = vf0 + 16 * j;
        cp_async16(rawV_u + (uint32_t)(vd * SRAW + f) * 4,
                   vbase + (size_t)vd * LEN + f);
    }
    cp_commit();
    cp_wait_all();
    __syncthreads();

    {   // pack K0/V0 -> buffer 0
        uint32_t* Kh = KhB;
        uint32_t* Vh = VhB;
        #pragma unroll
        for (int j = 0; j < 2; ++j) {
            int i = tid + j * NTHREADS;
            int c2 = i >> 4, f = i & 15;
            const float4 a = *(const float4*)(rk + (2 * c2) * SRAW + 4 * f);
            const float4 d = *(const float4*)(rk + (2 * c2 + 1) * SRAW + 4 * f);
            uint4 w;
            w.x = pack_h2(a.x, d.x); w.y = pack_h2(a.y, d.y);
            w.z = pack_h2(a.z, d.z); w.w = pack_h2(a.w, d.w);
            *(uint4*)(Kh + c2 * SKH + 4 * f) = w;
        }
        #pragma unroll
        for (int j = 0; j < 4; ++j) {
            int i = tid + j * NTHREADS;
            int d = i & 63, f = i >> 6;         // s = 4f
            const float4 v = *(const float4*)(rv + d * SRAW + 4 * f);
            Vh[(2 * f) * SVH + d]     = pack_h2(v.x, v.y);
            Vh[(2 * f + 1) * SVH + d] = pack_h2(v.z, v.w);
        }
    }
    __syncthreads();   // packed[0] visible; raw buffers free

    // issue raw K1/V1 (lands during tile 0 S-phase)
    #pragma unroll
    for (int j = 0; j < 4; ++j) {
        int c = kc0 + (j & 1) + 32 * (j >> 1);
        cp_async16(rawK_u + (uint32_t)(c * SRAW + kf) * 4,
                   kbase + (size_t)c * LEN + BN + kf);
    }
    #pragma unroll
    for (int j = 0; j < 4; ++j) {
        int f = vf0 + 16 * j;
        cp_async16(rawV_u + (uint32_t)(vd * SRAW + f) * 4,
                   vbase + (size_t)vd * LEN + BN + f);
    }
    cp_commit();

    float l[2][2] = {{0.f, 0.f}, {0.f, 0.f}};
    float o[2][8][4];
    #pragma unroll
    for (int rb = 0; rb < 2; ++rb)
        #pragma unroll
        for (int n = 0; n < 8; ++n)
            #pragma unroll
            for (int s = 0; s < 4; ++s) o[rb][n][s] = 0.f;

    for (int it = 0; it < NKV; ++it) {
        const uint32_t* Kh = KhB + (it & 1) * PKBUF;
        const uint32_t* Vh = VhB + (it & 1) * PKBUF;

        // ---- S = (Q*scale) @ K^T : 32 rows x 64 kv per warp, k=16/step ----
        float sc[2][8][4];
        #pragma unroll
        for (int rb = 0; rb < 2; ++rb)
            #pragma unroll
            for (int n = 0; n < 8; ++n)
                #pragma unroll
                for (int s = 0; s < 4; ++s) sc[rb][n][s] = 0.f;

        #pragma unroll
        for (int kk = 0; kk < 4; ++kk) {
            const int r0 = kk * 8 + quad;
            uint32_t qa[2][4];
            #pragma unroll
            for (int rb = 0; rb < 2; ++rb) {
                int tA = warp * 32 + rb * 16 + g;
                qa[rb][0] = Qh[r0 * SQH + tA];
                qa[rb][1] = Qh[r0 * SQH + tA + 8];
                qa[rb][2] = Qh[(r0 + 4) * SQH + tA];
                qa[rb][3] = Qh[(r0 + 4) * SQH + tA + 8];
            }
            #pragma unroll
            for (int n = 0; n < 8; ++n) {
                uint32_t b0 = Kh[r0 * SKH + n * 8 + g];
                uint32_t b1 = Kh[(r0 + 4) * SKH + n * 8 + g];
                mma_f16(sc[0][n], qa[0], b0, b1);
                mma_f16(sc[1][n], qa[1], b0, b1);
            }
        }

        // ---- pipelined pack: raw[it+1] -> packed[(it+1)&1] ----
        // Safe without a barrier: each thread reads ONLY raw cells its own
        // cp.asyncs wrote (self-matched mapping), ordered by its own wait_group.
        if (it + 1 < NKV) {
            cp_wait_all();     // own raw[it+1] copies complete
            uint32_t* Kn = KhB + ((it + 1) & 1) * PKBUF;
            uint32_t* Vn = VhB + ((it + 1) & 1) * PKBUF;
            #pragma unroll
            for (int j = 0; j < 2; ++j) {
                int i = tid + j * NTHREADS;
                int c2 = i >> 4, f = i & 15;
                const float4 a = *(const float4*)(rk + (2 * c2) * SRAW + 4 * f);
                const float4 d = *(const float4*)(rk + (2 * c2 + 1) * SRAW + 4 * f);
                uint4 w;
                w.x = pack_h2(a.x, d.x); w.y = pack_h2(a.y, d.y);
                w.z = pack_h2(a.z, d.z); w.w = pack_h2(a.w, d.w);
                *(uint4*)(Kn + c2 * SKH + 4 * f) = w;
            }
            #pragma unroll
            for (int j = 0; j < 4; ++j) {
                int i = tid + j * NTHREADS;
                int d = i & 63, f = i >> 6;
                const float4 v = *(const float4*)(rv + d * SRAW + 4 * f);
                Vn[(2 * f) * SVH + d]     = pack_h2(v.x, v.y);
                Vn[(2 * f + 1) * SVH + d] = pack_h2(v.z, v.w);
            }
        }

        // ---- fused exp + C->A register repack + PV, per k-chunk ----
        #pragma unroll
        for (int kk = 0; kk < 4; ++kk) {
            const int r0 = kk * 8 + quad;
            uint32_t pa[2][4];
            #pragma unroll
            for (int rb = 0; rb < 2; ++rb) {
                float e00 = ex2f(sc[rb][2 * kk][0]);
                float e01 = ex2f(sc[rb][2 * kk][1]);
                float e02 = ex2f(sc[rb][2 * kk][2]);
                float e03 = ex2f(sc[rb][2 * kk][3]);
                float e10 = ex2f(sc[rb][2 * kk + 1][0]);
                float e11 = ex2f(sc[rb][2 * kk + 1][1]);
                float e12 = ex2f(sc[rb][2 * kk + 1][2]);
                float e13 = ex2f(sc[rb][2 * kk + 1][3]);
                l[rb][0] += (e00 + e01) + (e10 + e11);
                l[rb][1] += (e02 + e03) + (e12 + e13);
                pa[rb][0] = pack_h2(e00, e01);
                pa[rb][1] = pack_h2(e02, e03);
                pa[rb][2] = pack_h2(e10, e11);
                pa[rb][3] = pack_h2(e12, e13);
            }
            #pragma unroll
            for (int n = 0; n < 8; ++n) {
                uint32_t b0 = Vh[r0 * SVH + n * 8 + g];
                uint32_t b1 = Vh[(r0 + 4) * SVH + n * 8 + g];
                mma_f16(o[0][n], pa[0], b0, b1);
                mma_f16(o[1][n], pa[1], b0, b1);
            }
        }

        __syncthreads();       // packed[it+1] visible; raw reusable; packed[it] free

        if (it + 2 < NKV) {    // issue raw[it+2]; lands during tile it+1 S-phase
            const int s1 = (it + 2) * BN;
            #pragma unroll
            for (int j = 0; j < 4; ++j) {
                int c = kc0 + (j & 1) + 32 * (j >> 1);
                cp_async16(rawK_u + (uint32_t)(c * SRAW + kf) * 4,
                           kbase + (size_t)c * LEN + s1 + kf);
            }
            #pragma unroll
            for (int j = 0; j < 4; ++j) {
                int f = vf0 + 16 * j;
                cp_async16(rawV_u + (uint32_t)(vd * SRAW + f) * 4,
                           vbase + (size_t)vd * LEN + s1 + f);
            }
            cp_commit();
        }
    }

    // ---- finalize: quad-reduce l, normalize, store ----
    float inv[2][2];
    #pragma unroll
    for (int rb = 0; rb < 2; ++rb)
        #pragma unroll
        for (int h = 0; h < 2; ++h) {
            l[rb][h] += __shfl_xor_sync(0xffffffffu, l[rb][h], 1);
            l[rb][h] += __shfl_xor_sync(0xffffffffu, l[rb][h], 2);
            inv[rb][h] = 1.f / l[rb][h];
        }

    float* obase = out + ((size_t)b * 512 + (size_t)hd * 64) * LEN + t0 + warp * 32;
    #pragma unroll
    for (int rb = 0; rb < 2; ++rb)
        #pragma unroll
        for (int n = 0; n < 8; ++n) {
            const int row0 = rb * 16 + g;
            const int d0 = n * 8 + quad * 2;
            obase[(size_t)d0 * LEN + row0]           = o[rb][n][0] * inv[rb][0];
            obase[(size_t)(d0 + 1) * LEN + row0]     = o[rb][n][1] * inv[rb][0];
            obase[(size_t)d0 * LEN + row0 + 8]       = o[rb][n][2] * inv[rb][1];
            obase[(size_t)(d0 + 1) * LEN + row0 + 8] = o[rb][n][3] * inv[rb][1];
        }
}

extern "C" void kernel_launch(void* const* d_in, const int* in_sizes, int n_in,
                              void* d_out, int out_size) {
    const float* qkv = (const float*)d_in[0];
    float* out = (float*)d_out;

    cudaFuncSetAttribute(attn_f16_pipe,
                         cudaFuncAttributeMaxDynamicSharedMemorySize, SMEM_BYTES);

    dim3 grid(LEN / BM, 32);
    attn_f16_pipe<<<grid, NTHREADS, SMEM_BYTES>>>(qkv, out);
}